// round 9
// baseline (speedup 1.0000x reference)
#include <cuda_runtime.h>
#include <cuda_bf16.h>
#include <math.h>
#include <stdint.h>

// ---------------------------------------------------------------------------
// SemanticConsistencyLoss — R9: R8 dataflow + full address strength-reduction.
//  * warp w owns labels {lab&15==w}; float4 acc[10] register accumulators.
//  * staging tile [128ch][33px] bank-perfect; 2 buffers; 1 barrier/tile.
//  * NEW: hoisted per-thread pointers, immediate-offset STS/LDS, 2x-unrolled
//    main loop (static buffer selection), guard once per 2 tiles.
// ---------------------------------------------------------------------------

#define NUM_CLASSES 150
#define CH        256
#define HCH       128
#define NPIX      (512 * 512)
#define CHUNKS    74
#define PPC       3584            // multiple of 64 -> ntiles even (112 / 16)
#define TPX       32
#define TPB       512
#define TSTRIDE   33
#define TILE_W    (HCH * TSTRIDE) // 4224 words per buffer

__device__ float g_psums[2][CHUNKS][NUM_CLASSES][CH];
__device__ float g_pcnts[2][CHUNKS][NUM_CLASSES];
__device__ float g_csq[NUM_CLASSES];

#define SM_CNT      (2 * TILE_W)
#define SMEM_FLOATS (SM_CNT + 152)
#define SMEM_BYTES  (SMEM_FLOATS * 4)   // ~34.4 KB

#define ACC_CASE(k)                                                        \
    case k: acc[k].x += v0; acc[k].y += v1; acc[k].z += v2; acc[k].w += v3; break;

// stage tile from regs into buffer BUF (0/1): all offsets compile-time imms
#define STAGE(BUF)                                                         \
    do {                                                                   \
        float* d = tsp + (BUF) * TILE_W;                                   \
        d[0] = r[0].x; d[1] = r[0].y; d[2] = r[0].z; d[3] = r[0].w;        \
        d[64 * TSTRIDE + 0] = r[1].x; d[64 * TSTRIDE + 1] = r[1].y;        \
        d[64 * TSTRIDE + 2] = r[1].z; d[64 * TSTRIDE + 3] = r[1].w;        \
    } while (0)

#define PREFETCH()                                                         \
    do {                                                                   \
        r[0] = *(const float4*)g0;  r[1] = *(const float4*)g1;             \
        g0 += TPX;  g1 += TPX;                                             \
        mylbl = *lp;  lp += TPX;                                           \
    } while (0)

// RMW tile in buffer BUF: immediate channel-slice offsets
#define RMW(BUF)                                                           \
    do {                                                                   \
        const int lblcur = stagelbl;                                       \
        unsigned m = __ballot_sync(0xffffffffu, (lblcur & 15) == wid);     \
        const float* rb = trp + (BUF) * TILE_W;                            \
        while (m) {                                                        \
            const int j = __ffs(m) - 1;                                    \
            m &= m - 1;                                                    \
            const int row = __shfl_sync(0xffffffffu, lblcur, j);           \
            const float* s = rb + j;                                       \
            const float v0 = s[0];                                         \
            const float v1 = s[32 * TSTRIDE];                              \
            const float v2 = s[64 * TSTRIDE];                              \
            const float v3 = s[96 * TSTRIDE];                              \
            switch (row >> 4) {                                            \
                ACC_CASE(0) ACC_CASE(1) ACC_CASE(2) ACC_CASE(3)            \
                ACC_CASE(4) ACC_CASE(5) ACC_CASE(6) ACC_CASE(7)            \
                ACC_CASE(8) ACC_CASE(9)                                    \
            }                                                              \
        }                                                                  \
    } while (0)

__global__ void __launch_bounds__(TPB, 2)
accum_kernel(const float* __restrict__ src, const float* __restrict__ trg,
             const int* __restrict__ slab, const int* __restrict__ tlab) {
    extern __shared__ float smf[];
    int* cnt = (int*)(smf + SM_CNT);

    const int chunk = blockIdx.x;
    const int tsel  = blockIdx.y;
    const int chalf = blockIdx.z;
    const float* __restrict__ F =
        (tsel ? trg : src) + (size_t)chalf * HCH * NPIX;
    const int*   __restrict__ L = tsel ? tlab : slab;

    const int tid  = threadIdx.x;
    const int wid  = tid >> 5;
    const int lane = tid & 31;

    if (tid < NUM_CLASSES) cnt[tid] = 0;
    __syncthreads();

    const int pbase  = chunk * PPC;
    const int psz    = min(PPC, NPIX - pbase);
    const int ntiles = psz / TPX;       // 112 or 16 (always even)

    if (chalf == 0) {
        for (int i = tid; i < psz; i += TPB)
            atomicAdd(&cnt[L[pbase + i]], 1);
    }

    float4 acc[10];
#pragma unroll
    for (int k = 0; k < 10; ++k) acc[k] = make_float4(0.f, 0.f, 0.f, 0.f);

    // ---- hoisted per-thread pointers ----
    const int ch0 = tid >> 3;           // 0..63
    const int p4  = tid & 7;
    const float* g0 = F + (size_t)ch0 * NPIX + pbase + p4 * 4;
    const float* g1 = g0 + (size_t)64 * NPIX;            // channel ch0+64
    const int*   lp = L + pbase + lane;
    float* tsp = smf + ch0 * TSTRIDE + p4 * 4;           // stage base
    const float* trp = smf + lane * TSTRIDE;             // RMW read base

    float4 r[2];
    int mylbl, stagelbl;
    PREFETCH();                          // tile 0

    for (int t = 0; t < ntiles; t += 2) {
        // ---- tile t (buffer 0) ----
        STAGE(0);
        stagelbl = mylbl;
        __syncthreads();
        PREFETCH();                      // tile t+1 (exists: ntiles even)
        RMW(0);

        // ---- tile t+1 (buffer 1) ----
        STAGE(1);
        stagelbl = mylbl;
        __syncthreads();
        if (t + 2 < ntiles) PREFETCH();  // tile t+2
        RMW(1);
    }
    __syncthreads();

    // ---- epilogue: registers -> partial scratch ----
    const int nk = (wid < 6) ? 10 : 9;
#pragma unroll
    for (int k = 0; k < 10; ++k) {
        if (k < nk) {
            const int cls = 16 * k + wid;
            float* o = &g_psums[tsel][chunk][cls][chalf * HCH];
            o[lane]      = acc[k].x;
            o[lane + 32] = acc[k].y;
            o[lane + 64] = acc[k].z;
            o[lane + 96] = acc[k].w;
        }
    }
    if (chalf == 0 && tid < NUM_CLASSES)
        g_pcnts[tsel][chunk][tid] = (float)cnt[tid];
}

__global__ void reduce_kernel() {
    const int cidx = blockIdx.x;
    const int ch   = threadIdx.x;

    float ss = 0.0f, st = 0.0f;
#pragma unroll
    for (int k = 0; k < CHUNKS; ++k) {
        ss += g_psums[0][k][cidx][ch];
        st += g_psums[1][k][cidx][ch];
    }
    float cs = 0.0f, ctn = 0.0f;
#pragma unroll
    for (int k = 0; k < CHUNKS; ++k) {
        cs  += g_pcnts[0][k][cidx];
        ctn += g_pcnts[1][k][cidx];
    }
    float d = ss / (cs + 1e-8f) - st / (ctn + 1e-8f);

    __shared__ float red[CH];
    red[ch] = d * d;
    __syncthreads();
#pragma unroll
    for (int s = CH / 2; s > 0; s >>= 1) {
        if (ch < s) red[ch] += red[ch + s];
        __syncthreads();
    }
    if (ch == 0) g_csq[cidx] = red[0];
}

__global__ void final_kernel(float* out) {
    const int l = threadIdx.x;
    float s = 0.0f;
#pragma unroll
    for (int i = l; i < NUM_CLASSES; i += 32) s += g_csq[i];
#pragma unroll
    for (int o = 16; o > 0; o >>= 1) s += __shfl_down_sync(0xffffffffu, s, o);
    if (l == 0) out[0] = sqrtf(s);
}

extern "C" void kernel_launch(void* const* d_in, const int* in_sizes, int n_in,
                              void* d_out, int out_size) {
    const float* src = (const float*)d_in[0];
    const float* trg = (const float*)d_in[1];
    const int*   sl  = (const int*)d_in[2];
    const int*   tl  = (const int*)d_in[3];
    float* out = (float*)d_out;

    cudaFuncSetAttribute(accum_kernel,
                         cudaFuncAttributeMaxDynamicSharedMemorySize,
                         SMEM_BYTES);

    dim3 grid(CHUNKS, 2, 2);   // 296 CTAs = one wave at occ 2
    accum_kernel<<<grid, TPB, SMEM_BYTES>>>(src, trg, sl, tl);
    reduce_kernel<<<NUM_CLASSES, CH>>>();
    final_kernel<<<1, 32>>>(out);
}

// round 10
// speedup vs baseline: 1.0912x; 1.0912x over previous
#include <cuda_runtime.h>
#include <cuda_bf16.h>
#include <math.h>
#include <stdint.h>

// ---------------------------------------------------------------------------
// SemanticConsistencyLoss — R10: R8 (measured best) + XOR-swizzled [px][ch]
// staging tile so the RMW read is a single LDS.128 per pixel.
//  * warp w owns labels {lab&15==w}; float4 acc[10] register accumulators,
//    lane owns channel quad 4*lane..4*lane+3 (contiguous).
//  * tile word(px,ch) = px*128 + 4*((ch>>2)^(px>>2)) + (ch&3):
//      - stage: 8 scalar STS, all 32 banks distinct (conflict-free)
//      - RMW:   LDS.128, quarter-warp within one 128B row (conflict-free)
//  * double-buffered, 1 barrier/tile, register prefetch, occ 2 (32 warps/SM).
// ---------------------------------------------------------------------------

#define NUM_CLASSES 150
#define CH        256
#define HCH       128
#define NPIX      (512 * 512)
#define CHUNKS    74
#define PPC       3584            // 74*3584 >= NPIX, multiple of 32
#define TPX       32
#define TPB       512
#define TILE_W    (TPX * HCH)     // 4096 words per buffer (16 KB)

__device__ float g_psums[2][CHUNKS][NUM_CLASSES][CH];
__device__ float g_pcnts[2][CHUNKS][NUM_CLASSES];
__device__ float g_csq[NUM_CLASSES];

// smem floats: tile[2][4096] | cnt[152]
#define SM_CNT      (2 * TILE_W)
#define SMEM_FLOATS (SM_CNT + 152)
#define SMEM_BYTES  (SMEM_FLOATS * 4)   // ~33.4 KB

#define ACC_CASE(k)                                                        \
    case k: acc[k].x += v.x; acc[k].y += v.y; acc[k].z += v.z; acc[k].w += v.w; break;

__global__ void __launch_bounds__(TPB, 2)
accum_kernel(const float* __restrict__ src, const float* __restrict__ trg,
             const int* __restrict__ slab, const int* __restrict__ tlab) {
    extern __shared__ float smf[];
    float* tiles = smf;                 // [2][32px][128ch] swizzled
    int*   cnt   = (int*)(smf + SM_CNT);

    const int chunk = blockIdx.x;
    const int tsel  = blockIdx.y;
    const int chalf = blockIdx.z;
    const float* __restrict__ F =
        (tsel ? trg : src) + (size_t)chalf * HCH * NPIX;
    const int*   __restrict__ L = tsel ? tlab : slab;

    const int tid  = threadIdx.x;
    const int wid  = tid >> 5;          // owns labels lab&15 == wid
    const int lane = tid & 31;

    if (tid < NUM_CLASSES) cnt[tid] = 0;
    __syncthreads();

    const int pbase  = chunk * PPC;
    const int psz    = min(PPC, NPIX - pbase);
    const int ntiles = psz / TPX;       // 112 (last chunk: 16)

    // ---- label histogram (integer-exact, one CTA per chunk/tensor) ----
    if (chalf == 0) {
        for (int i = tid; i < psz; i += TPB)
            atomicAdd(&cnt[L[pbase + i]], 1);
    }

    // ---- register accumulators: class 16k+wid, channels 4*lane..4*lane+3 ----
    float4 acc[10];
#pragma unroll
    for (int k = 0; k < 10; ++k) acc[k] = make_float4(0.f, 0.f, 0.f, 0.f);

    // ---- register prefetch of tile 0 ----
    float4 r[2];
    int mylbl;
    {
#pragma unroll
        for (int i = 0; i < 2; ++i) {
            int q = tid + TPB * i;
            int ch = q >> 3, p4 = q & 7;
            r[i] = *(const float4*)(F + (size_t)ch * NPIX + pbase + p4 * 4);
        }
        mylbl = L[pbase + lane];
    }

    for (int t = 0; t < ntiles; ++t) {
        float* tb = tiles + (t & 1) * TILE_W;

        // ---- stage: scalar stores, bank = 4*((ch>>2)^p4) + (ch&3), distinct ----
#pragma unroll
        for (int i = 0; i < 2; ++i) {
            int q = tid + TPB * i;
            int ch = q >> 3, p4 = q & 7;
            float* d = tb + (4 * p4) * HCH + 4 * ((ch >> 2) ^ p4) + (ch & 3);
            d[0]       = r[i].x;   // px 4*p4+0
            d[HCH]     = r[i].y;   // px 4*p4+1
            d[2 * HCH] = r[i].z;
            d[3 * HCH] = r[i].w;
        }
        const int lblcur = mylbl;
        __syncthreads();   // one barrier per tile (double buffer -> safe)

        // ---- prefetch next tile ----
        if (t + 1 < ntiles) {
            const int p0 = pbase + (t + 1) * TPX;
#pragma unroll
            for (int i = 0; i < 2; ++i) {
                int q = tid + TPB * i;
                int ch = q >> 3, p4 = q & 7;
                r[i] = *(const float4*)(F + (size_t)ch * NPIX + p0 + p4 * 4);
            }
            mylbl = L[p0 + lane];
        }

        // ---- accumulate: one LDS.128 + 4 FADD per owned pixel ----
        unsigned m = __ballot_sync(0xffffffffu, (lblcur & 15) == wid);
        while (m) {
            const int j = __ffs(m) - 1;
            m &= m - 1;
            const int row = __shfl_sync(0xffffffffu, lblcur, j);
            const float4 v =
                *(const float4*)(tb + j * HCH + 4 * (lane ^ (j >> 2)));
            switch (row >> 4) {        // warp-uniform branch
                ACC_CASE(0) ACC_CASE(1) ACC_CASE(2) ACC_CASE(3) ACC_CASE(4)
                ACC_CASE(5) ACC_CASE(6) ACC_CASE(7) ACC_CASE(8) ACC_CASE(9)
            }
        }
    }
    __syncthreads();

    // ---- epilogue: registers -> partial scratch (STG.128, coalesced) ----
    const int nk = (wid < 6) ? 10 : 9;   // classes 16k+wid <= 149
#pragma unroll
    for (int k = 0; k < 10; ++k) {
        if (k < nk) {
            const int cls = 16 * k + wid;
            float* o = &g_psums[tsel][chunk][cls][chalf * HCH];
            *(float4*)(o + 4 * lane) = acc[k];
        }
    }
    if (chalf == 0 && tid < NUM_CLASSES)
        g_pcnts[tsel][chunk][tid] = (float)cnt[tid];
}

__global__ void reduce_kernel() {
    const int cidx = blockIdx.x;    // class
    const int ch   = threadIdx.x;   // channel

    float ss = 0.0f, st = 0.0f;
#pragma unroll
    for (int k = 0; k < CHUNKS; ++k) {
        ss += g_psums[0][k][cidx][ch];
        st += g_psums[1][k][cidx][ch];
    }
    float cs = 0.0f, ctn = 0.0f;
#pragma unroll
    for (int k = 0; k < CHUNKS; ++k) {
        cs  += g_pcnts[0][k][cidx];
        ctn += g_pcnts[1][k][cidx];
    }
    float d = ss / (cs + 1e-8f) - st / (ctn + 1e-8f);

    __shared__ float red[CH];
    red[ch] = d * d;
    __syncthreads();
#pragma unroll
    for (int s = CH / 2; s > 0; s >>= 1) {
        if (ch < s) red[ch] += red[ch + s];
        __syncthreads();
    }
    if (ch == 0) g_csq[cidx] = red[0];
}

__global__ void final_kernel(float* out) {
    const int l = threadIdx.x;
    float s = 0.0f;
#pragma unroll
    for (int i = l; i < NUM_CLASSES; i += 32) s += g_csq[i];
#pragma unroll
    for (int o = 16; o > 0; o >>= 1) s += __shfl_down_sync(0xffffffffu, s, o);
    if (l == 0) out[0] = sqrtf(s);
}

extern "C" void kernel_launch(void* const* d_in, const int* in_sizes, int n_in,
                              void* d_out, int out_size) {
    const float* src = (const float*)d_in[0];   // src_fea  [1,256,512,512] f32
    const float* trg = (const float*)d_in[1];   // trg_fea
    const int*   sl  = (const int*)d_in[2];     // src_labels [1,512,512] i32
    const int*   tl  = (const int*)d_in[3];     // trg_pseudo_labels
    float* out = (float*)d_out;

    cudaFuncSetAttribute(accum_kernel,
                         cudaFuncAttributeMaxDynamicSharedMemorySize,
                         SMEM_BYTES);

    dim3 grid(CHUNKS, 2, 2);   // 296 CTAs = one wave at occ 2
    accum_kernel<<<grid, TPB, SMEM_BYTES>>>(src, trg, sl, tl);
    reduce_kernel<<<NUM_CLASSES, CH>>>();
    final_kernel<<<1, 32>>>(out);
}

// round 11
// speedup vs baseline: 1.1418x; 1.0464x over previous
#include <cuda_runtime.h>
#include <cuda_bf16.h>
#include <math.h>
#include <stdint.h>

// ---------------------------------------------------------------------------
// SemanticConsistencyLoss — R11: R8 (measured-best accum) + labels cached in
// smem (LDS instead of per-tile LDG in the ballot dependency) + reduce/final
// merged via ticket (one fewer launch).
//  * warp w owns labels {lab&15==w}; float4 acc[10] register accumulators.
//  * staging tile [128ch][33px] bank-perfect; double-buffered; 1 barrier/tile.
// ---------------------------------------------------------------------------

#define NUM_CLASSES 150
#define CH        256
#define HCH       128
#define NPIX      (512 * 512)
#define CHUNKS    74
#define PPC       3584            // 74*3584 >= NPIX, multiple of 32
#define TPX       32
#define TPB       512
#define TSTRIDE   33
#define TILE_W    (HCH * TSTRIDE) // 4224 words per buffer

__device__ float g_psums[2][CHUNKS][NUM_CLASSES][CH];
__device__ float g_pcnts[2][CHUNKS][NUM_CLASSES];
__device__ float g_csq[NUM_CLASSES];
__device__ unsigned int g_ticket = 0;

// smem floats: tile[2][4224] | lbl[3584] | cnt[152]
#define SM_LBL      (2 * TILE_W)
#define SM_CNT      (SM_LBL + PPC)
#define SMEM_FLOATS (SM_CNT + 152)
#define SMEM_BYTES  (SMEM_FLOATS * 4)   // ~48.7 KB -> occ 2

#define ACC_CASE(k)                                                        \
    case k: acc[k].x += v0; acc[k].y += v1; acc[k].z += v2; acc[k].w += v3; break;

__global__ void __launch_bounds__(TPB, 2)
accum_kernel(const float* __restrict__ src, const float* __restrict__ trg,
             const int* __restrict__ slab, const int* __restrict__ tlab) {
    extern __shared__ float smf[];
    float* tiles = smf;                 // [2][128][33]
    int*   lbl_s = (int*)(smf + SM_LBL);
    int*   cnt   = (int*)(smf + SM_CNT);

    const int chunk = blockIdx.x;
    const int tsel  = blockIdx.y;
    const int chalf = blockIdx.z;
    const float* __restrict__ F =
        (tsel ? trg : src) + (size_t)chalf * HCH * NPIX;
    const int*   __restrict__ L = tsel ? tlab : slab;

    const int tid  = threadIdx.x;
    const int wid  = tid >> 5;          // owns labels lab&15 == wid
    const int lane = tid & 31;

    if (tid < NUM_CLASSES) cnt[tid] = 0;
    __syncthreads();

    const int pbase  = chunk * PPC;
    const int psz    = min(PPC, NPIX - pbase);
    const int ntiles = psz / TPX;       // 112 (last chunk: 16)

    // ---- cache labels in smem + histogram (integer-exact) ----
    for (int i = tid; i < psz; i += TPB) {
        int l = L[pbase + i];
        lbl_s[i] = l;
        if (chalf == 0) atomicAdd(&cnt[l], 1);
    }
    __syncthreads();

    // ---- register accumulators: class 16k+wid, channels lane+{0,32,64,96} ----
    float4 acc[10];
#pragma unroll
    for (int k = 0; k < 10; ++k) acc[k] = make_float4(0.f, 0.f, 0.f, 0.f);

    // ---- register prefetch of tile 0 ----
    float4 r[2];
    int mylbl;
    {
#pragma unroll
        for (int i = 0; i < 2; ++i) {
            int q = tid + TPB * i;
            int ch = q >> 3, p4 = q & 7;
            r[i] = *(const float4*)(F + (size_t)ch * NPIX + pbase + p4 * 4);
        }
        mylbl = lbl_s[lane];
    }

    for (int t = 0; t < ntiles; ++t) {
        float* tb = tiles + (t & 1) * TILE_W;

        // ---- stage: bank-perfect scalar stores ----
#pragma unroll
        for (int i = 0; i < 2; ++i) {
            int q = tid + TPB * i;
            int ch = q >> 3, p4 = q & 7;
            float* d = tb + ch * TSTRIDE + p4 * 4;
            d[0] = r[i].x; d[1] = r[i].y; d[2] = r[i].z; d[3] = r[i].w;
        }
        const int lblcur = mylbl;
        __syncthreads();   // one barrier per tile (double buffer -> safe)

        // ---- prefetch next tile (label now from smem: short latency) ----
        if (t + 1 < ntiles) {
            const int p0 = pbase + (t + 1) * TPX;
#pragma unroll
            for (int i = 0; i < 2; ++i) {
                int q = tid + TPB * i;
                int ch = q >> 3, p4 = q & 7;
                r[i] = *(const float4*)(F + (size_t)ch * NPIX + p0 + p4 * 4);
            }
            mylbl = lbl_s[(t + 1) * TPX + lane];
        }

        // ---- accumulate into registers: warp-uniform class switch ----
        unsigned m = __ballot_sync(0xffffffffu, (lblcur & 15) == wid);
        while (m) {
            const int j = __ffs(m) - 1;
            m &= m - 1;
            const int row = __shfl_sync(0xffffffffu, lblcur, j);
            const float* srcc = tb + lane * TSTRIDE + j;   // bank = lane+j
            const float v0 = srcc[0];
            const float v1 = srcc[32 * TSTRIDE];
            const float v2 = srcc[64 * TSTRIDE];
            const float v3 = srcc[96 * TSTRIDE];
            switch (row >> 4) {        // warp-uniform branch
                ACC_CASE(0) ACC_CASE(1) ACC_CASE(2) ACC_CASE(3) ACC_CASE(4)
                ACC_CASE(5) ACC_CASE(6) ACC_CASE(7) ACC_CASE(8) ACC_CASE(9)
            }
        }
    }
    __syncthreads();

    // ---- epilogue: registers -> partial scratch (coalesced per lane) ----
    const int nk = (wid < 6) ? 10 : 9;   // classes 16k+wid <= 149
#pragma unroll
    for (int k = 0; k < 10; ++k) {
        if (k < nk) {
            const int cls = 16 * k + wid;
            float* o = &g_psums[tsel][chunk][cls][chalf * HCH];
            o[lane]      = acc[k].x;
            o[lane + 32] = acc[k].y;
            o[lane + 64] = acc[k].z;
            o[lane + 96] = acc[k].w;
        }
    }
    if (chalf == 0 && tid < NUM_CLASSES)
        g_pcnts[tsel][chunk][tid] = (float)cnt[tid];
}

// reduce + final merged: last block (ticket) computes the Frobenius norm.
__global__ void reduce_kernel(float* out) {
    const int cidx = blockIdx.x;    // class
    const int ch   = threadIdx.x;   // channel

    float ss = 0.0f, st = 0.0f;
#pragma unroll
    for (int k = 0; k < CHUNKS; ++k) {
        ss += g_psums[0][k][cidx][ch];
        st += g_psums[1][k][cidx][ch];
    }
    float cs = 0.0f, ctn = 0.0f;
#pragma unroll
    for (int k = 0; k < CHUNKS; ++k) {
        cs  += g_pcnts[0][k][cidx];
        ctn += g_pcnts[1][k][cidx];
    }
    float d = ss / (cs + 1e-8f) - st / (ctn + 1e-8f);

    __shared__ float red[CH];
    __shared__ unsigned int is_last;
    red[ch] = d * d;
    __syncthreads();
#pragma unroll
    for (int s = CH / 2; s > 0; s >>= 1) {
        if (ch < s) red[ch] += red[ch + s];
        __syncthreads();
    }
    if (ch == 0) {
        g_csq[cidx] = red[0];
        __threadfence();
        unsigned int t = atomicAdd(&g_ticket, 1u);
        is_last = (t == (unsigned)gridDim.x - 1u) ? 1u : 0u;
    }
    __syncthreads();

    if (is_last) {
        if (ch < 32) {
            float s = 0.0f;
#pragma unroll
            for (int i = ch; i < NUM_CLASSES; i += 32)
                s += __ldcg(&g_csq[i]);
#pragma unroll
            for (int o = 16; o > 0; o >>= 1)
                s += __shfl_down_sync(0xffffffffu, s, o);
            if (ch == 0) {
                out[0] = sqrtf(s);
                g_ticket = 0;          // reset for next graph replay
            }
        }
    }
}

extern "C" void kernel_launch(void* const* d_in, const int* in_sizes, int n_in,
                              void* d_out, int out_size) {
    const float* src = (const float*)d_in[0];   // src_fea  [1,256,512,512] f32
    const float* trg = (const float*)d_in[1];   // trg_fea
    const int*   sl  = (const int*)d_in[2];     // src_labels [1,512,512] i32
    const int*   tl  = (const int*)d_in[3];     // trg_pseudo_labels
    float* out = (float*)d_out;

    cudaFuncSetAttribute(accum_kernel,
                         cudaFuncAttributeMaxDynamicSharedMemorySize,
                         SMEM_BYTES);

    dim3 grid(CHUNKS, 2, 2);   // 296 CTAs = one wave at occ 2
    accum_kernel<<<grid, TPB, SMEM_BYTES>>>(src, trg, sl, tl);
    reduce_kernel<<<NUM_CLASSES, CH>>>(out);
}